// round 9
// baseline (speedup 1.0000x reference)
#include <cuda_runtime.h>
#include <cuda_fp16.h>
#include <cstdint>
#include <math.h>

#define B_ 1024
#define D_ 512
#define K_ 256
#define J_ 1024   // reduction length: [x^2 | x]

// ---------------- scratch (no allocations allowed) ----------------
__device__ __half g_Bv[K_ * J_];  // [k][j]: j<512 -> 0.5*s2, j>=512 -> -m*s2
__device__ float g_C[K_];         // 0.5 * sum_d m^2 s2
__device__ int   g_count;         // monotonic grid-barrier ticket counter

__device__ __forceinline__ uint32_t smem_u32(const void* p) {
    uint32_t a;
    asm("{ .reg .u64 t; cvta.to.shared.u64 t, %1; cvt.u32.u64 %0, t; }" : "=r"(a) : "l"(p));
    return a;
}
__device__ __forceinline__ void cpasync16(uint32_t dst, const void* src) {
    asm volatile("cp.async.cg.shared.global [%0], [%1], 16;\n" :: "r"(dst), "l"(src) : "memory");
}

// ---------------------------------------------------------------------------
// Fused persistent kernel. Grid = 256 CTAs x 256 threads (2 CTAs/SM, all
// resident -> internal grid barrier is deadlock-free).
//
// Phase 1: CTA k (k = blockIdx.x) builds V row k + C[k]; zeroes its 4KB of out.
// Barrier (monotonic ticket counter; each launch adds exactly 256).
// Phase 2: CTA -> (m, n, z); BM=64, BN=64, KSPLIT=4 (KPER=256).
//   A tile computed DIRECTLY from x (fp32 LDG -> square/convert -> fp16 smem).
//   B tile cp.async from g_Bv. One __syncthreads, 16 MMA steps, atomic epilogue.
// ---------------------------------------------------------------------------
#define BM 64
#define BN 64
#define KPER 256
#define ROWB 528      // 256 fp16 (512B) + 16B pad: 33 chunks/row, 33%8==1 -> conflict-free
#define OFF_A 0
#define OFF_B (BM * ROWB)                  // 33792
#define SMEM_TOTAL (2 * BM * ROWB)         // 67584

__device__ __forceinline__ void ldm4(uint32_t* f, uint32_t addr) {
    asm volatile("ldmatrix.sync.aligned.m8n8.x4.shared.b16 {%0,%1,%2,%3}, [%4];"
                 : "=r"(f[0]), "=r"(f[1]), "=r"(f[2]), "=r"(f[3]) : "r"(addr));
}
__device__ __forceinline__ void mma16816(float* c, const uint32_t* a, uint32_t b0, uint32_t b1) {
    asm volatile("mma.sync.aligned.m16n8k16.row.col.f32.f16.f16.f32 "
                 "{%0,%1,%2,%3}, {%4,%5,%6,%7}, {%8,%9}, {%0,%1,%2,%3};"
                 : "+f"(c[0]), "+f"(c[1]), "+f"(c[2]), "+f"(c[3])
                 : "r"(a[0]), "r"(a[1]), "r"(a[2]), "r"(a[3]), "r"(b0), "r"(b1));
}

struct __align__(8) half2x2 { __half2 a, b; };

__global__ __launch_bounds__(256, 2) void fused_kernel(const float* __restrict__ x,
                                                       const float* __restrict__ means,
                                                       const float* __restrict__ rho,
                                                       float* __restrict__ out) {
    extern __shared__ char dyn[];
    __shared__ float Cs[BN];
    __shared__ float red8[8];

    const int bid = blockIdx.x;
    const int tid = threadIdx.x;
    const int wid = tid >> 5, lane = tid & 31;

    // ---------------- Phase 1: V row + C for k = bid; zero out slice -------
    {
        const int k = bid;
        const float2* m2 = (const float2*)(means + (size_t)k * D_);
        const float2* r2 = (const float2*)(rho   + (size_t)k * D_);
        float2 m = m2[tid];
        float2 r = r2[tid];
        float s0 = __logf(1.0f + __expf(r.x));
        float s1 = __logf(1.0f + __expf(r.y));
        float s20 = s0 * s0, s21 = s1 * s1;
        const int d = tid * 2;
        *(__half2*)&g_Bv[(size_t)k * J_ + d]      = __floats2half2_rn(0.5f * s20, 0.5f * s21);
        *(__half2*)&g_Bv[(size_t)k * J_ + D_ + d] = __floats2half2_rn(-m.x * s20, -m.y * s21);
        float csum = 0.5f * (m.x * m.x * s20 + m.y * m.y * s21);
        #pragma unroll
        for (int off = 16; off > 0; off >>= 1)
            csum += __shfl_xor_sync(0xFFFFFFFFu, csum, off);
        if (lane == 0) red8[wid] = csum;

        // zero this CTA's 4KB slice of out
        ((float4*)out)[bid * 256 + tid] = make_float4(0.f, 0.f, 0.f, 0.f);

        __syncthreads();
        if (tid == 0) {
            float t = 0.f;
            #pragma unroll
            for (int i = 0; i < 8; i++) t += red8[i];
            g_C[k] = t;
        }
    }

    // ---------------- Grid barrier (monotonic ticket) -----------------------
    __threadfence();
    __syncthreads();
    if (tid == 0) {
        int ticket = atomicAdd(&g_count, 1);
        int target = (ticket & ~255) + 256;        // this launch's completion count
        while (*(volatile int*)&g_count < target) { }
    }
    __syncthreads();
    __threadfence();

    // ---------------- Phase 2: GEMM tile -----------------------------------
    const int m0 = (bid & 15) * BM;
    const int n0 = ((bid >> 4) & 3) * BN;
    const int z  = bid >> 6;                       // 0..3
    const int dz0 = (z & 1) * 256;                 // dim offset within x row
    const bool sq = (z < 2);                       // x^2 halves vs x halves
    const int kz0 = z * KPER;                      // offset in J-space for B

    const uint32_t sbase = smem_u32(dyn);

    // B tile via cp.async: 64 rows x 32 16B-chunks = 2048 -> 8 per thread
    {
        const char* baseB = (const char*)g_Bv;
        #pragma unroll
        for (int i = 0; i < 8; i++) {
            int idx = tid + i * 256;
            int r = idx >> 5, c = idx & 31;
            cpasync16(sbase + OFF_B + (uint32_t)(r * ROWB + c * 16),
                      baseB + ((size_t)(n0 + r) * J_ + kz0) * 2 + c * 16);
        }
        asm volatile("cp.async.commit_group;\n" ::: "memory");
    }

    // A tile direct from x: 64 rows x 64 float4 = 4096 -> 16 per thread
    {
        #pragma unroll
        for (int i = 0; i < 16; i++) {
            int idx = tid + i * 256;
            int r = idx >> 6, c = idx & 63;
            float4 v = *(const float4*)(x + (size_t)(m0 + r) * D_ + dz0 + c * 4);
            if (sq) { v.x *= v.x; v.y *= v.y; v.z *= v.z; v.w *= v.w; }
            half2x2 h;
            h.a = __floats2half2_rn(v.x, v.y);
            h.b = __floats2half2_rn(v.z, v.w);
            *(half2x2*)(dyn + OFF_A + r * ROWB + c * 8) = h;
        }
    }

    if (tid < BN) Cs[tid] = g_C[n0 + tid];

    asm volatile("cp.async.wait_group 0;\n" ::: "memory");
    __syncthreads();

    // MMA mainloop: warp tile 16x32, 8 warps = 4(M) x 2(N), 16 k-steps.
    const int mw = (wid & 3) * 16;
    const int nw = (wid >> 2) * 32;

    float acc[16];
    #pragma unroll
    for (int i = 0; i < 16; i++) acc[i] = 0.f;

    const uint32_t aB  = sbase + OFF_A + (uint32_t)((mw + (lane & 15)) * ROWB + (lane >> 4) * 16);
    const uint32_t b0B = sbase + OFF_B + (uint32_t)((nw + (lane & 7) + ((lane >> 4) << 3)) * ROWB
                                                    + (((lane >> 3) & 1) << 4));
    const uint32_t b1B = b0B + 16 * ROWB;

    #pragma unroll
    for (int kk = 0; kk < KPER / 16; kk++) {
        const uint32_t kbb = (uint32_t)(kk * 32);
        uint32_t aF[4], b0[4], b1[4];
        ldm4(aF, aB + kbb);
        ldm4(b0, b0B + kbb);
        ldm4(b1, b1B + kbb);
        mma16816(acc + 0,  aF, b0[0], b0[1]);
        mma16816(acc + 4,  aF, b0[2], b0[3]);
        mma16816(acc + 8,  aF, b1[0], b1[1]);
        mma16816(acc + 12, aF, b1[2], b1[3]);
    }

    // Epilogue: atomic accumulate (out zeroed in phase 1). z==0 adds bias C.
    const int row = lane >> 2;
    const int col = (lane & 3) * 2;
    const int gr0 = m0 + mw + row;
    const bool addc = (z == 0);
    #pragma unroll
    for (int j = 0; j < 4; j++) {
        const int gc = n0 + nw + j * 8 + col;
        const float cA = addc ? Cs[nw + j * 8 + col]     : 0.f;
        const float cB = addc ? Cs[nw + j * 8 + col + 1] : 0.f;
        float* oT = out + (size_t)gr0 * K_ + gc;
        float* oB = out + (size_t)(gr0 + 8) * K_ + gc;
        atomicAdd(oT + 0, acc[j * 4 + 0] + cA);
        atomicAdd(oT + 1, acc[j * 4 + 1] + cB);
        atomicAdd(oB + 0, acc[j * 4 + 2] + cA);
        atomicAdd(oB + 1, acc[j * 4 + 3] + cB);
    }
}

// ---------------------------------------------------------------------------
extern "C" void kernel_launch(void* const* d_in, const int* in_sizes, int n_in,
                              void* d_out, int out_size) {
    const float* x     = (const float*)d_in[0];
    const float* means = (const float*)d_in[1];
    const float* rho   = (const float*)d_in[2];
    float* out = (float*)d_out;

    cudaFuncSetAttribute(fused_kernel, cudaFuncAttributeMaxDynamicSharedMemorySize,
                         SMEM_TOTAL);
    fused_kernel<<<256, 256, SMEM_TOTAL>>>(x, means, rho, out);
}